// round 5
// baseline (speedup 1.0000x reference)
#include <cuda_runtime.h>
#include <cuda_bf16.h>
#include <math.h>
#include <stdint.h>

#define MAXN 50000
#define MAXE 800000
#define DIN 64
#define DOUT 128
#define KDIM 192
#define TE 128

// Scratch (device globals)
__device__ float g_ht[MAXN * DOUT];
__device__ float g_a[MAXE * 4];
__device__ float g_amax[MAXN * 4];
__device__ float g_denom[MAXN * 4];
// W_edges transposed + bf16-split: [n][k] pairs packed as u32 (lo = even k)
__device__ uint32_t g_Wh[DOUT * KDIM / 2];
__device__ uint32_t g_Wl[DOUT * KDIM / 2];

__device__ __forceinline__ void atomicMaxFloat(float* addr, float value) {
    if (value >= 0.0f) atomicMax((int*)addr, __float_as_int(value));
    else               atomicMin((unsigned int*)addr, __float_as_uint(value));
}

__device__ __forceinline__ void mma_bf16(float* d, const uint32_t* a, const uint32_t* b) {
    asm volatile(
        "mma.sync.aligned.m16n8k16.row.col.f32.bf16.bf16.f32 "
        "{%0,%1,%2,%3}, {%4,%5,%6,%7}, {%8,%9}, {%0,%1,%2,%3};"
        : "+f"(d[0]), "+f"(d[1]), "+f"(d[2]), "+f"(d[3])
        : "r"(a[0]), "r"(a[1]), "r"(a[2]), "r"(a[3]), "r"(b[0]), "r"(b[1]));
}

// split x -> (bf16 hi bits, bf16 lo bits)
__device__ __forceinline__ void bsplit(float x, uint16_t& h, uint16_t& l) {
    __nv_bfloat16 bh = __float2bfloat16_rn(x);
    float r = x - __bfloat162float(bh);
    __nv_bfloat16 bl = __float2bfloat16_rn(r);
    h = __bfloat16_as_ushort(bh);
    l = __bfloat16_as_ushort(bl);
}

// ---------------------------------------------------------------------------
// init: h_out = 0, amax = -inf, denom = 0
// ---------------------------------------------------------------------------
__global__ void init_all_kernel(float* h_out, int N) {
    int stride = gridDim.x * blockDim.x;
    int total_h = N * DOUT;
    for (int i = blockIdx.x * blockDim.x + threadIdx.x; i < total_h; i += stride)
        h_out[i] = 0.0f;
    int total_a = N * 4;
    for (int i = blockIdx.x * blockDim.x + threadIdx.x; i < total_a; i += stride) {
        g_amax[i] = -INFINITY;
        g_denom[i] = 0.0f;
    }
}

// ---------------------------------------------------------------------------
// W_edges -> transposed bf16 hi/lo split: g_Wh/g_Wl[n][k] (packed u32 pairs)
// ---------------------------------------------------------------------------
__global__ void wconv_kernel(const float* __restrict__ W_edges) {
    int i = blockIdx.x * blockDim.x + threadIdx.x;   // over 128 * 96
    if (i >= DOUT * KDIM / 2) return;
    int n  = i / (KDIM / 2);
    int kc = i % (KDIM / 2);
    float x0 = W_edges[(size_t)(2 * kc) * DOUT + n];
    float x1 = W_edges[(size_t)(2 * kc + 1) * DOUT + n];
    uint16_t h0, l0, h1, l1;
    bsplit(x0, h0, l0);
    bsplit(x1, h1, l1);
    g_Wh[i] = (uint32_t)h0 | ((uint32_t)h1 << 16);
    g_Wl[i] = (uint32_t)l0 | ((uint32_t)l1 << 16);
}

// ---------------------------------------------------------------------------
// node transform
// ---------------------------------------------------------------------------
__global__ void node_kernel(const float* __restrict__ nfeats,
                            const float* __restrict__ W_nodes,
                            const float* __restrict__ b_nodes,
                            int N) {
    __shared__ float Ws[DIN * DOUT];
    __shared__ float xs[DIN];
    int tid = threadIdx.x;
    for (int i = tid; i < DIN * DOUT / 4; i += 128)
        ((float4*)Ws)[i] = ((const float4*)W_nodes)[i];
    float b = b_nodes[tid];
    __syncthreads();
    for (int n = blockIdx.x; n < N; n += gridDim.x) {
        if (tid < DIN / 4)
            ((float4*)xs)[tid] = ((const float4*)(nfeats + (size_t)n * DIN))[tid];
        __syncthreads();
        float acc = b;
#pragma unroll
        for (int k = 0; k < DIN; k++)
            acc += xs[k] * Ws[k * DOUT + tid];
        g_ht[(size_t)n * DOUT + tid] = acc;
        __syncthreads();
    }
}

// ---------------------------------------------------------------------------
// Edge kernel: bf16 mma.sync (3-term split) GEMM + bias + leaky + attention
// 128 edges x 128 cols per block, 256 threads (8 warps).
// Warp w: m-rows [(w&3)*32, +32), n-cols [(w>>2)*64, +64).
// ---------------------------------------------------------------------------
#define ASTRIDE 400                  // bytes per 192-bf16 row (+4 pad pairs)
#define SO_AH 0                      // 128*400 = 51200
#define SO_AL 51200
#define SO_BH 102400
#define SO_BL 153600
#define SO_BS 204800                 // bias, 512B
#define SO_WAS 205312                // 128B
#define SO_SIDX 205440               // 512B
#define SO_DIDX 205952               // 512B
#define SO_TOTAL 206464
#define FSTRIDE 132                  // f32 staging row stride (words)

__global__ __launch_bounds__(256, 1)
void edge_kernel(const float* __restrict__ nfeats,
                 const float* __restrict__ efeats,
                 const int* __restrict__ src,
                 const int* __restrict__ dst,
                 const float* __restrict__ b_edges,
                 const float* __restrict__ W_attn,
                 float* __restrict__ f_out,
                 int E) {
    extern __shared__ char smem[];
    float* bs  = (float*)(smem + SO_BS);
    float* was = (float*)(smem + SO_WAS);
    int* sidx  = (int*)(smem + SO_SIDX);
    int* didx  = (int*)(smem + SO_DIDX);

    int tid  = threadIdx.x;
    int lane = tid & 31;
    int warp = tid >> 5;
    int e0   = blockIdx.x * TE;

    if (tid < DOUT) bs[tid] = b_edges[tid];
    if (tid < 32)
        was[tid] = W_attn[tid * 4] + W_attn[tid * 4 + 1]
                 + W_attn[tid * 4 + 2] + W_attn[tid * 4 + 3];
    if (tid < TE) {
        int e = e0 + tid;
        sidx[tid] = (e < E) ? src[e] : 0;
        didx[tid] = (e < E) ? dst[e] : 0;
    }
    __syncthreads();

    // --- gather + bf16-split A: rows = edges, cols = k (stack layout) ---
#pragma unroll
    for (int it = 0; it < 8; it++) {
        int i   = tid + it * 256;     // 0..2047
        int le  = i >> 4;
        int seg = i & 15;             // float4 index within 64-float chunk... (0..15 over 192? no:)
        // seg covers 16 float4 = 64 floats; map i to (le, seg48): 2048 = 128*16 — we need 48 segs!
        (void)seg;
        break;
    }
    // NOTE: 192 floats per row = 48 float4 segs -> 128*48 = 6144 tasks
    for (int i = tid; i < TE * 48; i += 256) {
        int le  = i / 48;
        int seg = i % 48;
        int e   = e0 + le;
        float4 v = make_float4(0.f, 0.f, 0.f, 0.f);
        if (seg < 16)
            v = ((const float4*)(nfeats + (size_t)sidx[le] * DIN))[seg];
        else if (seg < 32) {
            if (e < E) v = ((const float4*)(efeats + (size_t)e * DIN))[seg - 16];
        } else
            v = ((const float4*)(nfeats + (size_t)didx[le] * DIN))[seg - 32];
        uint16_t h0, l0, h1, l1, h2, l2, h3, l3;
        bsplit(v.x, h0, l0); bsplit(v.y, h1, l1);
        bsplit(v.z, h2, l2); bsplit(v.w, h3, l3);
        uint2 hv = make_uint2((uint32_t)h0 | ((uint32_t)h1 << 16),
                              (uint32_t)h2 | ((uint32_t)h3 << 16));
        uint2 lv = make_uint2((uint32_t)l0 | ((uint32_t)l1 << 16),
                              (uint32_t)l2 | ((uint32_t)l3 << 16));
        *(uint2*)(smem + SO_AH + le * ASTRIDE + seg * 8) = hv;
        *(uint2*)(smem + SO_AL + le * ASTRIDE + seg * 8) = lv;
    }
    // --- copy pre-split W (transposed [n][k]) into strided smem ---
    for (int i = tid; i < DOUT * (KDIM / 2); i += 256) {
        int r = i / (KDIM / 2);
        int c = i % (KDIM / 2);
        ((uint32_t*)(smem + SO_BH + r * ASTRIDE))[c] = g_Wh[i];
        ((uint32_t*)(smem + SO_BL + r * ASTRIDE))[c] = g_Wl[i];
    }
    __syncthreads();

    // --- mma mainloop ---
    int gid = lane >> 2;      // group id (0..7)
    int tig = lane & 3;       // thread in group
    int mrow = (warp & 3) * 32 + gid;
    int nrow = (warp >> 2) * 64 + gid;

    float acc[2][8][4];
#pragma unroll
    for (int mt = 0; mt < 2; mt++)
#pragma unroll
        for (int nt = 0; nt < 8; nt++)
#pragma unroll
            for (int q = 0; q < 4; q++) acc[mt][nt][q] = 0.0f;

#pragma unroll
    for (int kk = 0; kk < 12; kk++) {
        int kb = kk * 32 + tig * 4;   // byte offset within row
        uint32_t ah[2][4], al_[2][4], bh[8][2], bl_[8][2];
#pragma unroll
        for (int mt = 0; mt < 2; mt++) {
            const char* ba = smem + SO_AH + (mrow + mt * 16) * ASTRIDE + kb;
            ah[mt][0] = *(const uint32_t*)(ba);
            ah[mt][1] = *(const uint32_t*)(ba + 8 * ASTRIDE);
            ah[mt][2] = *(const uint32_t*)(ba + 16);
            ah[mt][3] = *(const uint32_t*)(ba + 8 * ASTRIDE + 16);
            const char* bl2 = smem + SO_AL + (mrow + mt * 16) * ASTRIDE + kb;
            al_[mt][0] = *(const uint32_t*)(bl2);
            al_[mt][1] = *(const uint32_t*)(bl2 + 8 * ASTRIDE);
            al_[mt][2] = *(const uint32_t*)(bl2 + 16);
            al_[mt][3] = *(const uint32_t*)(bl2 + 8 * ASTRIDE + 16);
        }
#pragma unroll
        for (int nt = 0; nt < 8; nt++) {
            const char* bb = smem + SO_BH + (nrow + nt * 8) * ASTRIDE + kb;
            bh[nt][0] = *(const uint32_t*)(bb);
            bh[nt][1] = *(const uint32_t*)(bb + 16);
            const char* bb2 = smem + SO_BL + (nrow + nt * 8) * ASTRIDE + kb;
            bl_[nt][0] = *(const uint32_t*)(bb2);
            bl_[nt][1] = *(const uint32_t*)(bb2 + 16);
        }
#pragma unroll
        for (int mt = 0; mt < 2; mt++)
#pragma unroll
            for (int nt = 0; nt < 8; nt++) {
                mma_bf16(acc[mt][nt], ah[mt], bh[nt]);
                mma_bf16(acc[mt][nt], ah[mt], bl_[nt]);
                mma_bf16(acc[mt][nt], al_[mt], bh[nt]);
            }
    }

    __syncthreads();   // everyone done reading A/B smem

    // --- stage accumulators to smem f32 tile [128][FSTRIDE] ---
    float* F = (float*)smem;
#pragma unroll
    for (int mt = 0; mt < 2; mt++)
#pragma unroll
        for (int nt = 0; nt < 8; nt++) {
            int r = (warp & 3) * 32 + mt * 16 + gid;
            int c = (warp >> 2) * 64 + nt * 8 + tig * 2;
            F[r * FSTRIDE + c]           = acc[mt][nt][0];
            F[r * FSTRIDE + c + 1]       = acc[mt][nt][1];
            F[(r + 8) * FSTRIDE + c]     = acc[mt][nt][2];
            F[(r + 8) * FSTRIDE + c + 1] = acc[mt][nt][3];
        }
    __syncthreads();

    // --- epilogue: 512 (edge, head) tasks over 256 threads ---
#pragma unroll
    for (int t = 0; t < 2; t++) {
        int task = tid + t * 256;
        int le = task >> 2;
        int h  = task & 3;
        int e  = e0 + le;
        const float* row = F + le * FSTRIDE + h * 32;
        float fv[32];
        float part = 0.0f;
#pragma unroll
        for (int jj = 0; jj < 32; jj++) {
            int j = (jj + h * 8) & 31;      // rotate to dodge bank conflicts
            float v = row[j] + bs[h * 32 + j];
            v = (v >= 0.f) ? v : 0.01f * v;
            fv[j] = v;
            part += v * was[j];
        }
        if (e < E) {
            float4* dstp = (float4*)(f_out + (size_t)e * DOUT + h * 32);
#pragma unroll
            for (int q = 0; q < 8; q++)
                dstp[q] = make_float4(fv[4 * q], fv[4 * q + 1],
                                      fv[4 * q + 2], fv[4 * q + 3]);
            g_a[(size_t)e * 4 + h] = part;
            atomicMaxFloat(&g_amax[(size_t)didx[le] * 4 + h], part);
        }
    }
}

// ---------------------------------------------------------------------------
__global__ void softmax_kernel(const int* __restrict__ dst, int E) {
    int stride = gridDim.x * blockDim.x;
    int total = E * 4;
    for (int i = blockIdx.x * blockDim.x + threadIdx.x; i < total; i += stride) {
        int e = i >> 2;
        int h = i & 3;
        int d = dst[e];
        float v = expf(g_a[i] - g_amax[d * 4 + h]);
        g_a[i] = v;
        atomicAdd(&g_denom[d * 4 + h], v);
    }
}

__global__ void scatter_kernel(const int* __restrict__ src,
                               const int* __restrict__ dst,
                               float* __restrict__ h_out,
                               int E) {
    int gwarp = (blockIdx.x * blockDim.x + threadIdx.x) >> 5;
    int lane  = threadIdx.x & 31;
    if (gwarp >= E) return;
    int s = src[gwarp];
    int d = dst[gwarp];
    int h = lane >> 3;
    float alpha = g_a[(size_t)gwarp * 4 + h] / g_denom[(size_t)d * 4 + h];
    float4 ht = *reinterpret_cast<const float4*>(g_ht + (size_t)s * DOUT + lane * 4);
    float4 v = make_float4(alpha * ht.x, alpha * ht.y, alpha * ht.z, alpha * ht.w);
    atomicAdd(reinterpret_cast<float4*>(h_out + (size_t)d * DOUT + lane * 4), v);
}

// ---------------------------------------------------------------------------
extern "C" void kernel_launch(void* const* d_in, const int* in_sizes, int n_in,
                              void* d_out, int out_size) {
    const float* nfeats  = (const float*)d_in[0];
    const float* efeats  = (const float*)d_in[1];
    const int*   src     = (const int*)d_in[2];
    const int*   dst     = (const int*)d_in[3];
    const float* W_nodes = (const float*)d_in[4];
    const float* b_nodes = (const float*)d_in[5];
    const float* W_edges = (const float*)d_in[6];
    const float* b_edges = (const float*)d_in[7];
    const float* W_attn  = (const float*)d_in[8];

    int N = in_sizes[0] / DIN;
    int E = in_sizes[2];

    float* h_out = (float*)d_out;
    float* f_out = (float*)d_out + (size_t)N * DOUT;

    cudaFuncSetAttribute(edge_kernel, cudaFuncAttributeMaxDynamicSharedMemorySize,
                         SO_TOTAL);

    // edge_kernel is launch #4 (ncu -s 5 -c 1 has been landing there)
    node_kernel<<<1024, 128>>>(nfeats, W_nodes, b_nodes, N);
    wconv_kernel<<<(DOUT * KDIM / 2 + 255) / 256, 256>>>(W_edges);
    init_all_kernel<<<512, 256>>>(h_out, N);
    int eblocks = (E + TE - 1) / TE;
    edge_kernel<<<eblocks, 256, SO_TOTAL>>>(nfeats, efeats, src, dst,
                                            b_edges, W_attn, f_out, E);
    softmax_kernel<<<1024, 256>>>(dst, E);
    scatter_kernel<<<(E * 32 + 255) / 256, 256>>>(src, dst, h_out, E);
}

// round 6
// speedup vs baseline: 1.2567x; 1.2567x over previous
#include <cuda_runtime.h>
#include <cuda_bf16.h>
#include <math.h>
#include <stdint.h>

#define MAXN 50000
#define MAXE 800000
#define DIN 64
#define DOUT 128
#define KDIM 192
#define TE 128

// Scratch (device globals)
__device__ float g_ht[MAXN * DOUT];
__device__ float g_a[MAXE * 4];
__device__ float g_amax[MAXN * 4];
__device__ float g_denom[MAXN * 4];
// W_edges transposed + bf16-split: [n][k] pairs packed as u32 (lo = even k)
__device__ uint32_t g_Wh[DOUT * KDIM / 2];
__device__ uint32_t g_Wl[DOUT * KDIM / 2];

__device__ __forceinline__ void atomicMaxFloat(float* addr, float value) {
    if (value >= 0.0f) atomicMax((int*)addr, __float_as_int(value));
    else               atomicMin((unsigned int*)addr, __float_as_uint(value));
}

__device__ __forceinline__ void mma_bf16(float* d, const uint32_t* a, const uint32_t* b) {
    asm volatile(
        "mma.sync.aligned.m16n8k16.row.col.f32.bf16.bf16.f32 "
        "{%0,%1,%2,%3}, {%4,%5,%6,%7}, {%8,%9}, {%0,%1,%2,%3};"
        : "+f"(d[0]), "+f"(d[1]), "+f"(d[2]), "+f"(d[3])
        : "r"(a[0]), "r"(a[1]), "r"(a[2]), "r"(a[3]), "r"(b[0]), "r"(b[1]));
}

__device__ __forceinline__ void ldsm_x4(uint32_t* r, uint32_t addr) {
    asm volatile("ldmatrix.sync.aligned.m8n8.x4.shared.b16 {%0,%1,%2,%3}, [%4];"
        : "=r"(r[0]), "=r"(r[1]), "=r"(r[2]), "=r"(r[3]) : "r"(addr));
}

__device__ __forceinline__ uint32_t smem_u32(const void* p) {
    uint32_t a;
    asm("{ .reg .u64 t; cvta.to.shared.u64 t, %1; cvt.u32.u64 %0, t; }"
        : "=r"(a) : "l"(p));
    return a;
}

// split x -> (bf16 hi bits, bf16 lo bits)
__device__ __forceinline__ void bsplit(float x, uint16_t& h, uint16_t& l) {
    __nv_bfloat16 bh = __float2bfloat16_rn(x);
    float r = x - __bfloat162float(bh);
    __nv_bfloat16 bl = __float2bfloat16_rn(r);
    h = __bfloat16_as_ushort(bh);
    l = __bfloat16_as_ushort(bl);
}

// ---------------------------------------------------------------------------
__global__ void init_all_kernel(float* h_out, int N) {
    int stride = gridDim.x * blockDim.x;
    int total_h = N * DOUT;
    for (int i = blockIdx.x * blockDim.x + threadIdx.x; i < total_h; i += stride)
        h_out[i] = 0.0f;
    int total_a = N * 4;
    for (int i = blockIdx.x * blockDim.x + threadIdx.x; i < total_a; i += stride) {
        g_amax[i] = -INFINITY;
        g_denom[i] = 0.0f;
    }
}

__global__ void wconv_kernel(const float* __restrict__ W_edges) {
    int i = blockIdx.x * blockDim.x + threadIdx.x;   // over 128 * 96
    if (i >= DOUT * KDIM / 2) return;
    int n  = i / (KDIM / 2);
    int kc = i % (KDIM / 2);
    float x0 = W_edges[(size_t)(2 * kc) * DOUT + n];
    float x1 = W_edges[(size_t)(2 * kc + 1) * DOUT + n];
    uint16_t h0, l0, h1, l1;
    bsplit(x0, h0, l0);
    bsplit(x1, h1, l1);
    g_Wh[i] = (uint32_t)h0 | ((uint32_t)h1 << 16);
    g_Wl[i] = (uint32_t)l0 | ((uint32_t)l1 << 16);
}

__global__ void node_kernel(const float* __restrict__ nfeats,
                            const float* __restrict__ W_nodes,
                            const float* __restrict__ b_nodes,
                            int N) {
    __shared__ float Ws[DIN * DOUT];
    __shared__ float xs[DIN];
    int tid = threadIdx.x;
    for (int i = tid; i < DIN * DOUT / 4; i += 128)
        ((float4*)Ws)[i] = ((const float4*)W_nodes)[i];
    float b = b_nodes[tid];
    __syncthreads();
    for (int n = blockIdx.x; n < N; n += gridDim.x) {
        if (tid < DIN / 4)
            ((float4*)xs)[tid] = ((const float4*)(nfeats + (size_t)n * DIN))[tid];
        __syncthreads();
        float acc = b;
#pragma unroll
        for (int k = 0; k < DIN; k++)
            acc += xs[k] * Ws[k * DOUT + tid];
        g_ht[(size_t)n * DOUT + tid] = acc;
        __syncthreads();
    }
}

// ---------------------------------------------------------------------------
// Edge kernel: bf16 mma.sync (3-term split) via ldmatrix, 512 threads.
// 128 edges x 128 cols per block; warp grid 4x4 (each warp 32x32 output).
// ---------------------------------------------------------------------------
#define ASTRIDE 400                  // bytes per 192-bf16 row (+16B pad)
#define SO_AH 0                      // 128*400 = 51200
#define SO_AL 51200
#define SO_BH 102400
#define SO_BL 153600
#define SO_BS 204800                 // bias, 512B
#define SO_WAS 205312                // 128B
#define SO_SIDX 205440               // 512B
#define SO_DIDX 205952               // 512B
#define SO_TOTAL 206464
#define FSTRIDE 132                  // f32 staging row stride (words)

__global__ __launch_bounds__(512, 1)
void edge_kernel(const float* __restrict__ nfeats,
                 const float* __restrict__ efeats,
                 const int* __restrict__ src,
                 const int* __restrict__ dst,
                 const float* __restrict__ b_edges,
                 const float* __restrict__ W_attn,
                 float* __restrict__ f_out,
                 int E) {
    extern __shared__ char smem[];
    float* bs  = (float*)(smem + SO_BS);
    float* was = (float*)(smem + SO_WAS);
    int* sidx  = (int*)(smem + SO_SIDX);
    int* didx  = (int*)(smem + SO_DIDX);

    int tid  = threadIdx.x;
    int lane = tid & 31;
    int warp = tid >> 5;
    int e0   = blockIdx.x * TE;
    uint32_t sb = smem_u32(smem);

    if (tid < DOUT) bs[tid] = b_edges[tid];
    if (tid < 32)
        was[tid] = W_attn[tid * 4] + W_attn[tid * 4 + 1]
                 + W_attn[tid * 4 + 2] + W_attn[tid * 4 + 3];
    if (tid < TE) {
        int e = e0 + tid;
        sidx[tid] = (e < E) ? src[e] : 0;
        didx[tid] = (e < E) ? dst[e] : 0;
    }
    __syncthreads();

    // --- gather + bf16-split A: 128 rows x 192 k (48 float4 segs per row) ---
    for (int i = tid; i < TE * 48; i += 512) {
        int le  = i / 48;
        int seg = i % 48;
        int e   = e0 + le;
        float4 v = make_float4(0.f, 0.f, 0.f, 0.f);
        if (seg < 16)
            v = ((const float4*)(nfeats + (size_t)sidx[le] * DIN))[seg];
        else if (seg < 32) {
            if (e < E) v = ((const float4*)(efeats + (size_t)e * DIN))[seg - 16];
        } else
            v = ((const float4*)(nfeats + (size_t)didx[le] * DIN))[seg - 32];
        uint16_t h0, l0, h1, l1, h2, l2, h3, l3;
        bsplit(v.x, h0, l0); bsplit(v.y, h1, l1);
        bsplit(v.z, h2, l2); bsplit(v.w, h3, l3);
        uint2 hv = make_uint2((uint32_t)h0 | ((uint32_t)h1 << 16),
                              (uint32_t)h2 | ((uint32_t)h3 << 16));
        uint2 lv = make_uint2((uint32_t)l0 | ((uint32_t)l1 << 16),
                              (uint32_t)l2 | ((uint32_t)l3 << 16));
        *(uint2*)(smem + SO_AH + le * ASTRIDE + seg * 8) = hv;
        *(uint2*)(smem + SO_AL + le * ASTRIDE + seg * 8) = lv;
    }
    // --- copy pre-split W ([n][k] u32 pairs) into strided smem, uint4 wide ---
    for (int i = tid; i < DOUT * 24; i += 512) {       // 24 uint4 per row
        int r = i / 24;
        int c = i % 24;
        uint4 vh = ((const uint4*)(g_Wh + r * (KDIM / 2)))[c];
        uint4 vl = ((const uint4*)(g_Wl + r * (KDIM / 2)))[c];
        *(uint4*)(smem + SO_BH + r * ASTRIDE + c * 16) = vh;
        *(uint4*)(smem + SO_BL + r * ASTRIDE + c * 16) = vl;
    }
    __syncthreads();

    // --- mma mainloop: warp (wm, wn) owns rows wm*32..+32, cols wn*32..+32 ---
    int wm = warp & 3;
    int wn = warp >> 2;
    int mrow0 = wm * 32;
    int nrow0 = wn * 32;

    // ldmatrix lane offsets
    uint32_t a_l_off = (uint32_t)((lane & 15) * ASTRIDE + (lane >> 4) * 16);
    uint32_t b_l_off = (uint32_t)(((lane & 7) + ((lane >> 4) << 3)) * ASTRIDE
                                + (((lane >> 3) & 1) << 4));

    float acc[2][4][4];
#pragma unroll
    for (int mt = 0; mt < 2; mt++)
#pragma unroll
        for (int nt = 0; nt < 4; nt++)
#pragma unroll
            for (int q = 0; q < 4; q++) acc[mt][nt][q] = 0.0f;

#pragma unroll
    for (int kk = 0; kk < 12; kk++) {
        uint32_t kb = kk * 32;
        uint32_t ah[2][4], al_[2][4];
        uint32_t bh[2][4], bl_[2][4];   // [pair][4 regs]: pair p covers n-tiles 2p, 2p+1
#pragma unroll
        for (int mt = 0; mt < 2; mt++) {
            uint32_t base = sb + (mrow0 + mt * 16) * ASTRIDE + kb + a_l_off;
            ldsm_x4(ah[mt], base + SO_AH);
            ldsm_x4(al_[mt], base + SO_AL);
        }
#pragma unroll
        for (int p = 0; p < 2; p++) {
            uint32_t base = sb + (nrow0 + p * 16) * ASTRIDE + kb + b_l_off;
            ldsm_x4(bh[p], base + SO_BH);
            ldsm_x4(bl_[p], base + SO_BL);
        }
#pragma unroll
        for (int mt = 0; mt < 2; mt++)
#pragma unroll
            for (int nt = 0; nt < 4; nt++) {
                const uint32_t* bhf = &bh[nt >> 1][(nt & 1) * 2];
                const uint32_t* blf = &bl_[nt >> 1][(nt & 1) * 2];
                mma_bf16(acc[mt][nt], ah[mt], bhf);
                mma_bf16(acc[mt][nt], ah[mt], blf);
                mma_bf16(acc[mt][nt], al_[mt], bhf);
            }
    }

    __syncthreads();   // done reading A/B smem

    // --- stage accumulators to smem f32 tile [128][FSTRIDE] ---
    float* F = (float*)smem;
    {
        int g   = lane >> 2;
        int tig = lane & 3;
#pragma unroll
        for (int mt = 0; mt < 2; mt++)
#pragma unroll
            for (int nt = 0; nt < 4; nt++) {
                int r = mrow0 + mt * 16 + g;
                int c = nrow0 + nt * 8 + tig * 2;
                F[r * FSTRIDE + c]           = acc[mt][nt][0];
                F[r * FSTRIDE + c + 1]       = acc[mt][nt][1];
                F[(r + 8) * FSTRIDE + c]     = acc[mt][nt][2];
                F[(r + 8) * FSTRIDE + c + 1] = acc[mt][nt][3];
            }
    }
    __syncthreads();

    // --- epilogue: 512 (edge, head) tasks, one per thread ---
    {
        int le = tid >> 2;
        int h  = tid & 3;
        int e  = e0 + le;
        const float* row = F + le * FSTRIDE + h * 32;
        float fv[32];
        float part = 0.0f;
#pragma unroll
        for (int jj = 0; jj < 32; jj++) {
            int j = (jj + h * 8) & 31;      // rotate to spread banks
            float v = row[j] + bs[h * 32 + j];
            v = (v >= 0.f) ? v : 0.01f * v;
            fv[j] = v;
            part += v * was[j];
        }
        if (e < E) {
            float4* dstp = (float4*)(f_out + (size_t)e * DOUT + h * 32);
#pragma unroll
            for (int q = 0; q < 8; q++)
                dstp[q] = make_float4(fv[4 * q], fv[4 * q + 1],
                                      fv[4 * q + 2], fv[4 * q + 3]);
            g_a[(size_t)e * 4 + h] = part;
            atomicMaxFloat(&g_amax[(size_t)didx[le] * 4 + h], part);
        }
    }
}

// ---------------------------------------------------------------------------
__global__ void softmax_kernel(const int* __restrict__ dst, int E) {
    int stride = gridDim.x * blockDim.x;
    int total = E * 4;
    for (int i = blockIdx.x * blockDim.x + threadIdx.x; i < total; i += stride) {
        int e = i >> 2;
        int h = i & 3;
        int d = dst[e];
        float v = expf(g_a[i] - g_amax[d * 4 + h]);
        g_a[i] = v;
        atomicAdd(&g_denom[d * 4 + h], v);
    }
}

__global__ void scatter_kernel(const int* __restrict__ src,
                               const int* __restrict__ dst,
                               float* __restrict__ h_out,
                               int E) {
    int gwarp = (blockIdx.x * blockDim.x + threadIdx.x) >> 5;
    int lane  = threadIdx.x & 31;
    if (gwarp >= E) return;
    int s = src[gwarp];
    int d = dst[gwarp];
    int h = lane >> 3;
    float alpha = g_a[(size_t)gwarp * 4 + h] / g_denom[(size_t)d * 4 + h];
    float4 ht = *reinterpret_cast<const float4*>(g_ht + (size_t)s * DOUT + lane * 4);
    float4 v = make_float4(alpha * ht.x, alpha * ht.y, alpha * ht.z, alpha * ht.w);
    atomicAdd(reinterpret_cast<float4*>(h_out + (size_t)d * DOUT + lane * 4), v);
}

// ---------------------------------------------------------------------------
extern "C" void kernel_launch(void* const* d_in, const int* in_sizes, int n_in,
                              void* d_out, int out_size) {
    const float* nfeats  = (const float*)d_in[0];
    const float* efeats  = (const float*)d_in[1];
    const int*   src     = (const int*)d_in[2];
    const int*   dst     = (const int*)d_in[3];
    const float* W_nodes = (const float*)d_in[4];
    const float* b_nodes = (const float*)d_in[5];
    const float* W_edges = (const float*)d_in[6];
    const float* b_edges = (const float*)d_in[7];
    const float* W_attn  = (const float*)d_in[8];

    int N = in_sizes[0] / DIN;
    int E = in_sizes[2];

    float* h_out = (float*)d_out;
    float* f_out = (float*)d_out + (size_t)N * DOUT;

    cudaFuncSetAttribute(edge_kernel, cudaFuncAttributeMaxDynamicSharedMemorySize,
                         SO_TOTAL);

    // edge_kernel stays launch #4 (ncu -s 5 -c 1 lands there)
    node_kernel<<<1024, 128>>>(nfeats, W_nodes, b_nodes, N);
    wconv_kernel<<<(DOUT * KDIM / 2 + 255) / 256, 256>>>(W_edges);
    init_all_kernel<<<512, 256>>>(h_out, N);
    int eblocks = (E + TE - 1) / TE;
    edge_kernel<<<eblocks, 512, SO_TOTAL>>>(nfeats, efeats, src, dst,
                                            b_edges, W_attn, f_out, E);
    softmax_kernel<<<1024, 256>>>(dst, E);
    scatter_kernel<<<(E * 32 + 255) / 256, 256>>>(src, dst, h_out, E);
}

// round 7
// speedup vs baseline: 1.3461x; 1.0712x over previous
#include <cuda_runtime.h>
#include <cuda_bf16.h>
#include <math.h>
#include <stdint.h>

#define MAXN 50000
#define MAXE 800000
#define DIN 64
#define DOUT 128
#define KDIM 192
#define TE 64                 // edges per block tile

// Scratch (device globals)
__device__ float g_ht[MAXN * DOUT];
__device__ float g_a[MAXE * 4];
__device__ float g_amax[MAXN * 4];
__device__ float g_denom[MAXN * 4];
// W_edges transposed + bf16-split: [n][k] pairs packed as u32 (lo bf16 = even k)
__device__ uint32_t g_Wh[DOUT * KDIM / 2];
__device__ uint32_t g_Wl[DOUT * KDIM / 2];

__device__ __forceinline__ void atomicMaxFloat(float* addr, float value) {
    if (value >= 0.0f) atomicMax((int*)addr, __float_as_int(value));
    else               atomicMin((unsigned int*)addr, __float_as_uint(value));
}

__device__ __forceinline__ void mma_bf16(float* d, const uint32_t* a, const uint32_t* b) {
    asm volatile(
        "mma.sync.aligned.m16n8k16.row.col.f32.bf16.bf16.f32 "
        "{%0,%1,%2,%3}, {%4,%5,%6,%7}, {%8,%9}, {%0,%1,%2,%3};"
        : "+f"(d[0]), "+f"(d[1]), "+f"(d[2]), "+f"(d[3])
        : "r"(a[0]), "r"(a[1]), "r"(a[2]), "r"(a[3]), "r"(b[0]), "r"(b[1]));
}

__device__ __forceinline__ void ldsm_x4(uint32_t* r, uint32_t addr) {
    asm volatile("ldmatrix.sync.aligned.m8n8.x4.shared.b16 {%0,%1,%2,%3}, [%4];"
        : "=r"(r[0]), "=r"(r[1]), "=r"(r[2]), "=r"(r[3]) : "r"(addr));
}

__device__ __forceinline__ uint32_t smem_u32(const void* p) {
    uint32_t a;
    asm("{ .reg .u64 t; cvta.to.shared.u64 t, %1; cvt.u32.u64 %0, t; }"
        : "=r"(a) : "l"(p));
    return a;
}

__device__ __forceinline__ void bsplit(float x, uint16_t& h, uint16_t& l) {
    __nv_bfloat16 bh = __float2bfloat16_rn(x);
    float r = x - __bfloat162float(bh);
    __nv_bfloat16 bl = __float2bfloat16_rn(r);
    h = __bfloat16_as_ushort(bh);
    l = __bfloat16_as_ushort(bl);
}

// ---------------------------------------------------------------------------
__global__ void init_all_kernel(float* h_out, int N) {
    int stride = gridDim.x * blockDim.x;
    int total_h = N * DOUT;
    for (int i = blockIdx.x * blockDim.x + threadIdx.x; i < total_h; i += stride)
        h_out[i] = 0.0f;
    int total_a = N * 4;
    for (int i = blockIdx.x * blockDim.x + threadIdx.x; i < total_a; i += stride) {
        g_amax[i] = -INFINITY;
        g_denom[i] = 0.0f;
    }
}

__global__ void wconv_kernel(const float* __restrict__ W_edges) {
    int i = blockIdx.x * blockDim.x + threadIdx.x;   // 128 * 96
    if (i >= DOUT * KDIM / 2) return;
    int n  = i / (KDIM / 2);
    int kc = i % (KDIM / 2);
    float x0 = W_edges[(size_t)(2 * kc) * DOUT + n];
    float x1 = W_edges[(size_t)(2 * kc + 1) * DOUT + n];
    uint16_t h0, l0, h1, l1;
    bsplit(x0, h0, l0);
    bsplit(x1, h1, l1);
    g_Wh[i] = (uint32_t)h0 | ((uint32_t)h1 << 16);
    g_Wl[i] = (uint32_t)l0 | ((uint32_t)l1 << 16);
}

__global__ void node_kernel(const float* __restrict__ nfeats,
                            const float* __restrict__ W_nodes,
                            const float* __restrict__ b_nodes,
                            int N) {
    __shared__ float Ws[DIN * DOUT];
    __shared__ float xs[DIN];
    int tid = threadIdx.x;
    for (int i = tid; i < DIN * DOUT / 4; i += 128)
        ((float4*)Ws)[i] = ((const float4*)W_nodes)[i];
    float b = b_nodes[tid];
    __syncthreads();
    for (int n = blockIdx.x; n < N; n += gridDim.x) {
        if (tid < DIN / 4)
            ((float4*)xs)[tid] = ((const float4*)(nfeats + (size_t)n * DIN))[tid];
        __syncthreads();
        float acc = b;
#pragma unroll
        for (int k = 0; k < DIN; k++)
            acc += xs[k] * Ws[k * DOUT + tid];
        g_ht[(size_t)n * DOUT + tid] = acc;
        __syncthreads();
    }
}

// ---------------------------------------------------------------------------
// Edge kernel: bf16 mma.sync (3-term split), K chunked into 3x64.
// 64 edges x 128 cols per block, 256 threads (8 warps; 2x4 grid, 32x32 each).
// Smem ~56KB -> 3 CTAs/SM for cross-CTA phase overlap.
// ---------------------------------------------------------------------------
#define ASTRIDE 144                  // bytes per 64-bf16 chunk row (+16B pad)
#define SO_AH 0                      // 64*144  = 9216
#define SO_AL 9216                   // 64*144  = 9216
#define SO_BH 18432                  // 128*144 = 18432
#define SO_BL 36864                  // 128*144 = 18432
#define SO_BS 55296                  // bias, 512B
#define SO_WAS 55808                 // 128B
#define SO_SIDX 55936                // 256B
#define SO_DIDX 56192                // 256B
#define SO_TOTAL 56448
#define FSTRIDE 132                  // f32 staging row stride (words)

__global__ __launch_bounds__(256, 3)
void edge_kernel(const float* __restrict__ nfeats,
                 const float* __restrict__ efeats,
                 const int* __restrict__ src,
                 const int* __restrict__ dst,
                 const float* __restrict__ b_edges,
                 const float* __restrict__ W_attn,
                 float* __restrict__ f_out,
                 int E) {
    extern __shared__ char smem[];
    float* bs  = (float*)(smem + SO_BS);
    float* was = (float*)(smem + SO_WAS);
    int* sidx  = (int*)(smem + SO_SIDX);
    int* didx  = (int*)(smem + SO_DIDX);

    int tid  = threadIdx.x;
    int lane = tid & 31;
    int warp = tid >> 5;
    int e0   = blockIdx.x * TE;
    uint32_t sb = smem_u32(smem);

    if (tid < DOUT) bs[tid] = b_edges[tid];
    if (tid < 32)
        was[tid] = W_attn[tid * 4] + W_attn[tid * 4 + 1]
                 + W_attn[tid * 4 + 2] + W_attn[tid * 4 + 3];
    if (tid < TE) {
        int e = e0 + tid;
        sidx[tid] = (e < E) ? src[e] : 0;
        didx[tid] = (e < E) ? dst[e] : 0;
    }

    // warp tile: 2 m-warps x 4 n-warps, 32x32 each
    int mrow0 = (warp & 1) * 32;
    int nrow0 = (warp >> 1) * 32;
    uint32_t a_l_off = (uint32_t)((lane & 15) * ASTRIDE + (lane >> 4) * 16);
    uint32_t b_l_off = (uint32_t)(((lane & 7) + ((lane >> 4) << 3)) * ASTRIDE
                                + (((lane >> 3) & 1) << 4));

    float acc[2][4][4];
#pragma unroll
    for (int mt = 0; mt < 2; mt++)
#pragma unroll
        for (int nt = 0; nt < 4; nt++)
#pragma unroll
            for (int q = 0; q < 4; q++) acc[mt][nt][q] = 0.0f;

#pragma unroll
    for (int c = 0; c < 3; c++) {
        __syncthreads();   // buffers free (or first pass: sidx/didx ready)

        // --- gather + bf16-split A chunk: 64 rows x 64 k ---
#pragma unroll
        for (int it = 0; it < 4; it++) {
            int i   = tid + it * 256;    // 0..1023
            int le  = i >> 4;
            int seg = i & 15;
            int e   = e0 + le;
            float4 v = make_float4(0.f, 0.f, 0.f, 0.f);
            if (c == 0)
                v = ((const float4*)(nfeats + (size_t)sidx[le] * DIN))[seg];
            else if (c == 1) {
                if (e < E) v = ((const float4*)(efeats + (size_t)e * DIN))[seg];
            } else
                v = ((const float4*)(nfeats + (size_t)didx[le] * DIN))[seg];
            uint16_t h0, l0, h1, l1, h2, l2, h3, l3;
            bsplit(v.x, h0, l0); bsplit(v.y, h1, l1);
            bsplit(v.z, h2, l2); bsplit(v.w, h3, l3);
            uint2 hv = make_uint2((uint32_t)h0 | ((uint32_t)h1 << 16),
                                  (uint32_t)h2 | ((uint32_t)h3 << 16));
            uint2 lv = make_uint2((uint32_t)l0 | ((uint32_t)l1 << 16),
                                  (uint32_t)l2 | ((uint32_t)l3 << 16));
            *(uint2*)(smem + SO_AH + le * ASTRIDE + seg * 8) = hv;
            *(uint2*)(smem + SO_AL + le * ASTRIDE + seg * 8) = lv;
        }
        // --- copy pre-split W chunk: rows n=0..127, kc in [32c, 32c+32) ---
#pragma unroll
        for (int it = 0; it < 8; it++) {
            int i = tid + it * 256;      // 0..2047
            int split = i >> 10;
            int n  = (i >> 3) & 127;
            int c4 = i & 7;
            const uint32_t* srcw = (split ? g_Wl : g_Wh) + n * (KDIM / 2) + 32 * c;
            uint4 v = ((const uint4*)srcw)[c4];
            *(uint4*)(smem + (split ? SO_BL : SO_BH) + n * ASTRIDE + c4 * 16) = v;
        }
        __syncthreads();

        // --- mma over this chunk: 4 k-iters of 16 ---
#pragma unroll
        for (int kk = 0; kk < 4; kk++) {
            uint32_t kb = kk * 32;
            uint32_t ah[2][4], al_[2][4], bh[2][4], bl_[2][4];
#pragma unroll
            for (int mt = 0; mt < 2; mt++) {
                uint32_t base = sb + (mrow0 + mt * 16) * ASTRIDE + kb + a_l_off;
                ldsm_x4(ah[mt], base + SO_AH);
                ldsm_x4(al_[mt], base + SO_AL);
            }
#pragma unroll
            for (int p = 0; p < 2; p++) {
                uint32_t base = sb + (nrow0 + p * 16) * ASTRIDE + kb + b_l_off;
                ldsm_x4(bh[p], base + SO_BH);
                ldsm_x4(bl_[p], base + SO_BL);
            }
#pragma unroll
            for (int mt = 0; mt < 2; mt++)
#pragma unroll
                for (int nt = 0; nt < 4; nt++) {
                    const uint32_t* bhf = &bh[nt >> 1][(nt & 1) * 2];
                    const uint32_t* blf = &bl_[nt >> 1][(nt & 1) * 2];
                    mma_bf16(acc[mt][nt], ah[mt], bhf);
                    mma_bf16(acc[mt][nt], ah[mt], blf);
                    mma_bf16(acc[mt][nt], al_[mt], bhf);
                }
        }
    }

    __syncthreads();   // done reading A/B smem

    // --- stage accumulators to smem f32 tile [64][FSTRIDE] (aliases buffers) ---
    float* F = (float*)smem;
    {
        int g   = lane >> 2;
        int tig = lane & 3;
#pragma unroll
        for (int mt = 0; mt < 2; mt++)
#pragma unroll
            for (int nt = 0; nt < 4; nt++) {
                int r = mrow0 + mt * 16 + g;
                int cc = nrow0 + nt * 8 + tig * 2;
                F[r * FSTRIDE + cc]           = acc[mt][nt][0];
                F[r * FSTRIDE + cc + 1]       = acc[mt][nt][1];
                F[(r + 8) * FSTRIDE + cc]     = acc[mt][nt][2];
                F[(r + 8) * FSTRIDE + cc + 1] = acc[mt][nt][3];
            }
    }
    __syncthreads();

    // --- epilogue: 256 (edge, head) tasks, one per thread ---
    {
        int le = tid >> 2;
        int h  = tid & 3;
        int e  = e0 + le;
        const float* row = F + le * FSTRIDE + h * 32;
        int rot = (h * 8 + le) & 31;     // conflict-free rotation (8h+le unique/warp)
        float fv[32];
        float part = 0.0f;
#pragma unroll
        for (int jj = 0; jj < 32; jj++) {
            int j = (jj + rot) & 31;
            float v = row[j] + bs[h * 32 + j];
            v = (v >= 0.f) ? v : 0.01f * v;
            fv[j] = v;
            part += v * was[j];
        }
        if (e < E) {
            float4* dstp = (float4*)(f_out + (size_t)e * DOUT + h * 32);
#pragma unroll
            for (int q = 0; q < 8; q++)
                dstp[q] = make_float4(fv[4 * q], fv[4 * q + 1],
                                      fv[4 * q + 2], fv[4 * q + 3]);
            g_a[(size_t)e * 4 + h] = part;
            atomicMaxFloat(&g_amax[(size_t)didx[le] * 4 + h], part);
        }
    }
}

// ---------------------------------------------------------------------------
__global__ void softmax_kernel(const int* __restrict__ dst, int E) {
    int stride = gridDim.x * blockDim.x;
    int total = E * 4;
    for (int i = blockIdx.x * blockDim.x + threadIdx.x; i < total; i += stride) {
        int e = i >> 2;
        int h = i & 3;
        int d = dst[e];
        float v = expf(g_a[i] - g_amax[d * 4 + h]);
        g_a[i] = v;
        atomicAdd(&g_denom[d * 4 + h], v);
    }
}

__global__ void scatter_kernel(const int* __restrict__ src,
                               const int* __restrict__ dst,
                               float* __restrict__ h_out,
                               int E) {
    int gwarp = (blockIdx.x * blockDim.x + threadIdx.x) >> 5;
    int lane  = threadIdx.x & 31;
    if (gwarp >= E) return;
    int s = src[gwarp];
    int d = dst[gwarp];
    int h = lane >> 3;
    float alpha = g_a[(size_t)gwarp * 4 + h] / g_denom[(size_t)d * 4 + h];
    float4 ht = *reinterpret_cast<const float4*>(g_ht + (size_t)s * DOUT + lane * 4);
    float4 v = make_float4(alpha * ht.x, alpha * ht.y, alpha * ht.z, alpha * ht.w);
    atomicAdd(reinterpret_cast<float4*>(h_out + (size_t)d * DOUT + lane * 4), v);
}

// ---------------------------------------------------------------------------
extern "C" void kernel_launch(void* const* d_in, const int* in_sizes, int n_in,
                              void* d_out, int out_size) {
    const float* nfeats  = (const float*)d_in[0];
    const float* efeats  = (const float*)d_in[1];
    const int*   src     = (const int*)d_in[2];
    const int*   dst     = (const int*)d_in[3];
    const float* W_nodes = (const float*)d_in[4];
    const float* b_nodes = (const float*)d_in[5];
    const float* W_edges = (const float*)d_in[6];
    const float* b_edges = (const float*)d_in[7];
    const float* W_attn  = (const float*)d_in[8];

    int N = in_sizes[0] / DIN;
    int E = in_sizes[2];

    float* h_out = (float*)d_out;
    float* f_out = (float*)d_out + (size_t)N * DOUT;

    cudaFuncSetAttribute(edge_kernel, cudaFuncAttributeMaxDynamicSharedMemorySize,
                         SO_TOTAL);

    // edge_kernel stays launch #4 (ncu -s 5 -c 1 lands there)
    node_kernel<<<1024, 128>>>(nfeats, W_nodes, b_nodes, N);
    wconv_kernel<<<(DOUT * KDIM / 2 + 255) / 256, 256>>>(W_edges);
    init_all_kernel<<<512, 256>>>(h_out, N);
    int eblocks = (E + TE - 1) / TE;
    edge_kernel<<<eblocks, 256, SO_TOTAL>>>(nfeats, efeats, src, dst,
                                            b_edges, W_attn, f_out, E);
    softmax_kernel<<<1024, 256>>>(dst, E);
    scatter_kernel<<<(E * 32 + 255) / 256, 256>>>(src, dst, h_out, E);
}